// round 10
// baseline (speedup 1.0000x reference)
#include <cuda_runtime.h>
#include <cuda_fp16.h>

#define NN 50000
#define EE 800000
#define DD 64
#define HH 4
#define OUTD 64
#define NSB 196   // (NN+255)/256
#define NODEB ((NN + 31) / 32)   // 1563 node-phase blocks

// ---------------------------------------------------------------------------
// Scratch (__device__ globals: allocation-free, zero-initialized at load;
// the fused gather/proj kernel re-zeroes the counters every launch so each
// graph replay starts clean)
// ---------------------------------------------------------------------------
__device__ int    g_degi[NN];        // out-degree over row (for nd)
__device__ int    g_cnt[NN];         // in-degree over col (for CSR)
__device__ int    g_off[NN + 1];     // CSR offsets by col
__device__ int    g_cursor[NN];      // scatter cursors
__device__ int4   g_edge[EE];        // {row, g01:half2, g23:half2, pad}, sorted by col
__device__ float  g_nd[NN];
__device__ float  g_a[NN * HH];      // h[v] . w1_h
__device__ float  g_bp[NN * HH];     // h[v] . w2_h
__device__ float  g_hn[NN * DD];     // nd[v] * h[v]
__device__ int    g_bsum[256];       // scan block sums
__device__ float4 g_wp[4096];        // repacked W_cat: wp[(kk*4+qr)*64+o]

// ---------------------------------------------------------------------------
// packed f32x2 helpers (FFMA2)
// ---------------------------------------------------------------------------
__device__ __forceinline__ unsigned long long pack2(float a, float b) {
    unsigned long long r;
    asm("mov.b64 %0, {%1, %2};" : "=l"(r) : "f"(a), "f"(b));
    return r;
}
__device__ __forceinline__ void ffma2(unsigned long long& d,
                                      unsigned long long a, unsigned long long b) {
    asm("fma.rn.f32x2 %0, %1, %2, %3;" : "=l"(d) : "l"(a), "l"(b), "l"(d));
}
__device__ __forceinline__ void unpack2(unsigned long long v, float& lo, float& hi) {
    asm("mov.b64 {%0, %1}, %2;" : "=f"(lo), "=f"(hi) : "l"(v));
}

// fast tanh: 1 - 2/(exp(2x)+1); MUFU.EX2 + MUFU.RCP, correct at +/-inf
__device__ __forceinline__ float fast_tanh(float x) {
    float e = __expf(2.0f * x);
    return 1.0f - __fdividef(2.0f, e + 1.0f);
}

// ---------------------------------------------------------------------------
// K1: degree counts (row for nd, col for CSR) + W_cat repack (independent)
// ---------------------------------------------------------------------------
__global__ void k_count(const int* __restrict__ ei,
                        const float* __restrict__ W_cat) {
    int e = blockIdx.x * blockDim.x + threadIdx.x;
    if (e < 4096) {
        int o = e & 63, qr = (e >> 6) & 3, kk = e >> 8;
        g_wp[e] = *reinterpret_cast<const float4*>(W_cat + o * 256 + qr * 64 + kk * 4);
    }
    if (e < EE) {
        atomicAdd(&g_degi[ei[e]], 1);
        atomicAdd(&g_cnt[ei[EE + e]], 1);
    }
}

// ---------------------------------------------------------------------------
// K2a: per-256-chunk sums
// ---------------------------------------------------------------------------
__global__ void k_scan1() {
    __shared__ int wsum[8];
    const int t = threadIdx.x, lane = t & 31, wid = t >> 5;
    int i = blockIdx.x * 256 + t;
    int v = (i < NN) ? g_cnt[i] : 0;
    int s = v;
    #pragma unroll
    for (int d = 16; d; d >>= 1) s += __shfl_xor_sync(0xffffffffu, s, d);
    if (lane == 0) wsum[wid] = s;
    __syncthreads();
    if (t == 0) {
        int tot = 0;
        #pragma unroll
        for (int w = 0; w < 8; w++) tot += wsum[w];
        g_bsum[blockIdx.x] = tot;
    }
}

// ---------------------------------------------------------------------------
// K2b (fused): blocks [0, NSB) finish the exclusive scan -> g_off, g_cursor;
//              blocks [NSB, NSB+NODEB) do per-node precompute:
//              nd, hn = nd*h, gate projections a/bp.
// ---------------------------------------------------------------------------
__global__ __launch_bounds__(256) void k_scan_node(const float* __restrict__ h,
                                                   const float* __restrict__ gate_w) {
    const int t = threadIdx.x, lane = t & 31, wid = t >> 5;

    if (blockIdx.x < NSB) {
        // ---- scan phase ----
        __shared__ int wsum[8];
        __shared__ int bpre_sh;

        int bv = (t < blockIdx.x) ? g_bsum[t] : 0;   // NSB <= 256
        #pragma unroll
        for (int d = 16; d; d >>= 1) bv += __shfl_xor_sync(0xffffffffu, bv, d);
        if (lane == 0) wsum[wid] = bv;
        __syncthreads();
        if (t == 0) {
            int s = 0;
            #pragma unroll
            for (int w = 0; w < 8; w++) s += wsum[w];
            bpre_sh = s;
        }
        __syncthreads();

        int i = blockIdx.x * 256 + t;
        int v = (i < NN) ? g_cnt[i] : 0;
        int x = v;
        #pragma unroll
        for (int d = 1; d < 32; d <<= 1) {
            int y = __shfl_up_sync(0xffffffffu, x, d);
            if (lane >= d) x += y;
        }
        __syncthreads();           // protect wsum reuse
        if (lane == 31) wsum[wid] = x;
        __syncthreads();
        int woff = 0;
        #pragma unroll
        for (int w = 0; w < 8; w++) if (w < wid) woff += wsum[w];
        int excl = bpre_sh + woff + x - v;
        if (i < NN) { g_off[i] = excl; g_cursor[i] = excl; }
        if (i == 0) g_off[NN] = EE;
        return;
    }

    // ---- node phase ----
    __shared__ float hs[32 * 64];
    __shared__ float ws[512];
    __shared__ float nds[32];
    const int v0 = (blockIdx.x - NSB) * 32;
    const int nval = (NN - v0 < 32) ? (NN - v0) : 32;
    const int lim4 = nval * 16;   // valid float4 count

    const float4* hg = reinterpret_cast<const float4*>(h + v0 * 64);
    float4* hs4 = reinterpret_cast<float4*>(hs);
    hs4[t]       = (t < lim4)       ? hg[t]       : make_float4(0, 0, 0, 0);
    hs4[t + 256] = (t + 256 < lim4) ? hg[t + 256] : make_float4(0, 0, 0, 0);
    if (t < 128) reinterpret_cast<float4*>(ws)[t] =
        reinterpret_cast<const float4*>(gate_w)[t];
    if (t < 32) {
        float ndv = 0.0f;
        if (t < nval) {
            ndv = rsqrtf(fmaxf((float)g_degi[v0 + t], 1.0f));
            g_nd[v0 + t] = ndv;
        }
        nds[t] = ndv;
    }
    __syncthreads();

    // hn = nd * h
    float4* hng = reinterpret_cast<float4*>(g_hn + v0 * 64);
    #pragma unroll
    for (int i = 0; i < 2; i++) {
        int idx = t + i * 256;
        if (idx < lim4) {
            float s = nds[idx >> 4];
            float4 hv = hs4[idx];
            hng[idx] = make_float4(s * hv.x, s * hv.y, s * hv.z, s * hv.w);
        }
    }

    // gate dots: thread = (node v = t>>3, k = t&7), hh = k&3, part = k>>2
    const int v = t >> 3, k = t & 7, hh = k & 3, part = k >> 2;
    const float4* hv4 = reinterpret_cast<const float4*>(hs + v * 64);
    const float4* w4 = reinterpret_cast<const float4*>(ws + hh * 128 + part * 64);
    float acc = 0.0f;
    #pragma unroll
    for (int i = 0; i < 16; i++) {
        float4 a = hv4[i], b = w4[i];
        acc += a.x * b.x + a.y * b.y + a.z * b.z + a.w * b.w;
    }
    if (v < nval) {
        if (part == 0) g_a[(v0 + v) * 4 + hh] = acc;
        else           g_bp[(v0 + v) * 4 + hh] = acc;
    }
}

// ---------------------------------------------------------------------------
// K4: scatter edges into col-sorted order; single packed 16B record per edge
//     {row, gates01:half2, gates23:half2}
// ---------------------------------------------------------------------------
__global__ void k_scatter(const int* __restrict__ ei,
                          const float* __restrict__ gate_b) {
    int e = blockIdx.x * blockDim.x + threadIdx.x;
    if (e >= EE) return;
    int row = ei[e];
    int col = ei[EE + e];
    float4 a  = *reinterpret_cast<const float4*>(g_a + row * 4);
    float4 bp = *reinterpret_cast<const float4*>(g_bp + col * 4);
    float4 gb = *reinterpret_cast<const float4*>(gate_b);
    float gx = fast_tanh(a.x + bp.x + gb.x);
    float gy = fast_tanh(a.y + bp.y + gb.y);
    float gz = fast_tanh(a.z + bp.z + gb.z);
    float gw = fast_tanh(a.w + bp.w + gb.w);
    __half2 h01 = __floats2half2_rn(gx, gy);
    __half2 h23 = __floats2half2_rn(gz, gw);
    int4 rec;
    rec.x = row;
    rec.y = *reinterpret_cast<int*>(&h01);
    rec.z = *reinterpret_cast<int*>(&h23);
    rec.w = 0;
    int pos = atomicAdd(&g_cursor[col], 1);
    g_edge[pos] = rec;
}

// ---------------------------------------------------------------------------
// K5 (fused gather + proj): block = 256 threads = 16 nodes (2 per warp,
//     16 lanes each). Phase 1: segment reduction into smem s_sh (no atomics,
//     no shuffles, one broadcast edge-record load + one LDG.128 of hn per
//     edge, FFMA2 accumulate). Phase 2: out = relu(s @ W^T + b) with FFMA2
//     and the repacked coalesced W. Also re-zeroes counters for next replay.
// ---------------------------------------------------------------------------
__global__ __launch_bounds__(256) void k_gather_proj(const float* __restrict__ b_cat,
                                                     float* __restrict__ out) {
    __shared__ float s_sh[16][256];
    __shared__ float red[3][16][64];
    const int t = threadIdx.x, lane = t & 31;
    const int half = lane >> 4, hl = lane & 15;
    const int v = ((t >> 5) << 1) + half;           // node-in-block 0..15
    const int n = blockIdx.x * 16 + v;              // NN % 16 == 0

    // counter re-zero for next replay (all readers of g_degi/g_cnt are done)
    {
        int gi = blockIdx.x * 256 + t;
        if (gi < NN) { g_degi[gi] = 0; g_cnt[gi] = 0; }
    }

    // ---- phase 1: gather ----
    const int beg = g_off[n], end = g_off[n + 1];
    const float ndc = g_nd[n];

    unsigned long long acc[8];
    #pragma unroll
    for (int i = 0; i < 8; i++) acc[i] = 0ULL;

    for (int base = beg; base < end; base += 4) {
        const int cnt = end - base;
        #pragma unroll
        for (int j = 0; j < 4; j++) {
            if (j < cnt) {
                const int4 er = g_edge[base + j];          // broadcast, 1 sector
                const int rj = er.x;
                __half2 h01 = *reinterpret_cast<const __half2*>(&er.y);
                __half2 h23 = *reinterpret_cast<const __half2*>(&er.z);
                float2 g01 = __half22float2(h01);
                float2 g23 = __half22float2(h23);
                const ulonglong2 hv =
                    *reinterpret_cast<const ulonglong2*>(g_hn + rj * 64 + 4 * hl);
                unsigned long long gp;
                gp = pack2(g01.x, g01.x); ffma2(acc[0], gp, hv.x); ffma2(acc[1], gp, hv.y);
                gp = pack2(g01.y, g01.y); ffma2(acc[2], gp, hv.x); ffma2(acc[3], gp, hv.y);
                gp = pack2(g23.x, g23.x); ffma2(acc[4], gp, hv.x); ffma2(acc[5], gp, hv.y);
                gp = pack2(g23.y, g23.y); ffma2(acc[6], gp, hv.x); ffma2(acc[7], gp, hv.y);
            }
        }
    }

    // write the node's 256-float s row into smem (layout [h][d], d = 4*hl..)
    float* sp = &s_sh[v][4 * hl];
    #pragma unroll
    for (int h2 = 0; h2 < 4; h2++) {
        float lo0, hi0, lo1, hi1;
        unpack2(acc[h2 * 2],     lo0, hi0);
        unpack2(acc[h2 * 2 + 1], lo1, hi1);
        *reinterpret_cast<float4*>(sp + h2 * 64) =
            make_float4(ndc * lo0, ndc * hi0, ndc * lo1, ndc * hi1);
    }
    __syncthreads();

    // ---- phase 2: projection ----
    const int o = t & 63, qr = t >> 6;
    const ulonglong2* wp = reinterpret_cast<const ulonglong2*>(g_wp);
    ulonglong2 wr[16];
    #pragma unroll
    for (int kk = 0; kk < 16; kk++) wr[kk] = wp[(kk * 4 + qr) * 64 + o];

    unsigned long long accP[16];
    #pragma unroll
    for (int vv = 0; vv < 16; vv++) accP[vv] = 0ULL;

    #pragma unroll
    for (int kk = 0; kk < 16; kk++) {
        ulonglong2 w2 = wr[kk];
        #pragma unroll
        for (int vv = 0; vv < 16; vv++) {
            ulonglong2 sv = *reinterpret_cast<const ulonglong2*>(
                &s_sh[vv][qr * 64 + kk * 4]);
            ffma2(accP[vv], w2.x, sv.x);
            ffma2(accP[vv], w2.y, sv.y);
        }
    }

    float accF[16];
    #pragma unroll
    for (int vv = 0; vv < 16; vv++) {
        float lo, hi;
        unpack2(accP[vv], lo, hi);
        accF[vv] = lo + hi;
    }

    if (qr > 0) {
        #pragma unroll
        for (int vv = 0; vv < 16; vv++) red[qr - 1][vv][o] = accF[vv];
    }
    __syncthreads();
    if (qr == 0) {
        float b = b_cat[o];
        #pragma unroll
        for (int vv = 0; vv < 16; vv++) {
            float sum = accF[vv] + red[0][vv][o] + red[1][vv][o] + red[2][vv][o] + b;
            out[(blockIdx.x * 16 + vv) * 64 + o] = fmaxf(sum, 0.0f);
        }
    }
}

// ---------------------------------------------------------------------------
extern "C" void kernel_launch(void* const* d_in, const int* in_sizes, int n_in,
                              void* d_out, int out_size) {
    const float* h      = (const float*)d_in[0];
    const int*   ei     = (const int*)d_in[1];
    const float* gate_w = (const float*)d_in[2];
    const float* gate_b = (const float*)d_in[3];
    const float* W_cat  = (const float*)d_in[4];
    const float* b_cat  = (const float*)d_in[5];
    float* out = (float*)d_out;

    k_count<<<(EE + 255) / 256, 256>>>(ei, W_cat);
    k_scan1<<<NSB, 256>>>();
    k_scan_node<<<NSB + NODEB, 256>>>(h, gate_w);
    k_scatter<<<(EE + 255) / 256, 256>>>(ei, gate_b);
    k_gather_proj<<<NN / 16, 256>>>(b_cat, out);
}

// round 11
// speedup vs baseline: 1.0293x; 1.0293x over previous
#include <cuda_runtime.h>
#include <cuda_fp16.h>

#define NN 50000
#define EE 800000
#define DD 64
#define HH 4
#define OUTD 64
#define NSB 196   // (NN+255)/256
#define NODEB ((NN + 31) / 32)   // 1563 node-phase blocks

// ---------------------------------------------------------------------------
// Scratch (__device__ globals: allocation-free, zero-initialized at load;
// k_proj re-zeroes the counters every launch so each graph replay starts clean)
// ---------------------------------------------------------------------------
__device__ int    g_degi[NN];        // out-degree over row (for nd)
__device__ int    g_cnt[NN];         // in-degree over col (for CSR)
__device__ int    g_off[NN + 1];     // CSR offsets by col
__device__ int    g_cursor[NN];      // scatter cursors
__device__ int4   g_edge[EE];        // {row, g01:half2, g23:half2, pad}, sorted by col
__device__ float  g_nd[NN];
__device__ float  g_a[NN * HH];      // h[v] . w1_h
__device__ float  g_bp[NN * HH];     // h[v] . w2_h
__device__ float  g_hn[NN * DD];     // nd[v] * h[v]
__device__ float  g_s[NN * HH * DD]; // aggregated (pre-projection) messages
__device__ int    g_bsum[256];       // scan block sums
__device__ float4 g_wp[4096];        // repacked W_cat: wp[(kk*4+qr)*64+o]

// ---------------------------------------------------------------------------
// packed f32x2 helpers (FFMA2)
// ---------------------------------------------------------------------------
__device__ __forceinline__ unsigned long long pack2(float a, float b) {
    unsigned long long r;
    asm("mov.b64 %0, {%1, %2};" : "=l"(r) : "f"(a), "f"(b));
    return r;
}
__device__ __forceinline__ void ffma2(unsigned long long& d,
                                      unsigned long long a, unsigned long long b) {
    asm("fma.rn.f32x2 %0, %1, %2, %3;" : "=l"(d) : "l"(a), "l"(b), "l"(d));
}
__device__ __forceinline__ void unpack2(unsigned long long v, float& lo, float& hi) {
    asm("mov.b64 {%0, %1}, %2;" : "=f"(lo), "=f"(hi) : "l"(v));
}

// fast tanh: 1 - 2/(exp(2x)+1); MUFU.EX2 + MUFU.RCP, correct at +/-inf
__device__ __forceinline__ float fast_tanh(float x) {
    float e = __expf(2.0f * x);
    return 1.0f - __fdividef(2.0f, e + 1.0f);
}

// ---------------------------------------------------------------------------
// K1: degree counts (row for nd, col for CSR) + W_cat repack (independent)
// ---------------------------------------------------------------------------
__global__ void k_count(const int* __restrict__ ei,
                        const float* __restrict__ W_cat) {
    int e = blockIdx.x * blockDim.x + threadIdx.x;
    if (e < 4096) {
        int o = e & 63, qr = (e >> 6) & 3, kk = e >> 8;
        g_wp[e] = *reinterpret_cast<const float4*>(W_cat + o * 256 + qr * 64 + kk * 4);
    }
    if (e < EE) {
        atomicAdd(&g_degi[ei[e]], 1);
        atomicAdd(&g_cnt[ei[EE + e]], 1);
    }
}

// ---------------------------------------------------------------------------
// K2a: per-256-chunk sums
// ---------------------------------------------------------------------------
__global__ void k_scan1() {
    __shared__ int wsum[8];
    const int t = threadIdx.x, lane = t & 31, wid = t >> 5;
    int i = blockIdx.x * 256 + t;
    int v = (i < NN) ? g_cnt[i] : 0;
    int s = v;
    #pragma unroll
    for (int d = 16; d; d >>= 1) s += __shfl_xor_sync(0xffffffffu, s, d);
    if (lane == 0) wsum[wid] = s;
    __syncthreads();
    if (t == 0) {
        int tot = 0;
        #pragma unroll
        for (int w = 0; w < 8; w++) tot += wsum[w];
        g_bsum[blockIdx.x] = tot;
    }
}

// ---------------------------------------------------------------------------
// K2b (fused): blocks [0, NSB) finish the exclusive scan -> g_off, g_cursor;
//              blocks [NSB, NSB+NODEB) do per-node precompute:
//              nd, hn = nd*h, gate projections a/bp.
// ---------------------------------------------------------------------------
__global__ __launch_bounds__(256) void k_scan_node(const float* __restrict__ h,
                                                   const float* __restrict__ gate_w) {
    const int t = threadIdx.x, lane = t & 31, wid = t >> 5;

    if (blockIdx.x < NSB) {
        // ---- scan phase ----
        __shared__ int wsum[8];
        __shared__ int bpre_sh;

        int bv = (t < blockIdx.x) ? g_bsum[t] : 0;   // NSB <= 256
        #pragma unroll
        for (int d = 16; d; d >>= 1) bv += __shfl_xor_sync(0xffffffffu, bv, d);
        if (lane == 0) wsum[wid] = bv;
        __syncthreads();
        if (t == 0) {
            int s = 0;
            #pragma unroll
            for (int w = 0; w < 8; w++) s += wsum[w];
            bpre_sh = s;
        }
        __syncthreads();

        int i = blockIdx.x * 256 + t;
        int v = (i < NN) ? g_cnt[i] : 0;
        int x = v;
        #pragma unroll
        for (int d = 1; d < 32; d <<= 1) {
            int y = __shfl_up_sync(0xffffffffu, x, d);
            if (lane >= d) x += y;
        }
        __syncthreads();           // protect wsum reuse
        if (lane == 31) wsum[wid] = x;
        __syncthreads();
        int woff = 0;
        #pragma unroll
        for (int w = 0; w < 8; w++) if (w < wid) woff += wsum[w];
        int excl = bpre_sh + woff + x - v;
        if (i < NN) { g_off[i] = excl; g_cursor[i] = excl; }
        if (i == 0) g_off[NN] = EE;
        return;
    }

    // ---- node phase ----
    __shared__ float hs[32 * 64];
    __shared__ float ws[512];
    __shared__ float nds[32];
    const int v0 = (blockIdx.x - NSB) * 32;
    const int nval = (NN - v0 < 32) ? (NN - v0) : 32;
    const int lim4 = nval * 16;   // valid float4 count

    const float4* hg = reinterpret_cast<const float4*>(h + v0 * 64);
    float4* hs4 = reinterpret_cast<float4*>(hs);
    hs4[t]       = (t < lim4)       ? hg[t]       : make_float4(0, 0, 0, 0);
    hs4[t + 256] = (t + 256 < lim4) ? hg[t + 256] : make_float4(0, 0, 0, 0);
    if (t < 128) reinterpret_cast<float4*>(ws)[t] =
        reinterpret_cast<const float4*>(gate_w)[t];
    if (t < 32) {
        float ndv = 0.0f;
        if (t < nval) {
            ndv = rsqrtf(fmaxf((float)g_degi[v0 + t], 1.0f));
            g_nd[v0 + t] = ndv;
        }
        nds[t] = ndv;
    }
    __syncthreads();

    // hn = nd * h
    float4* hng = reinterpret_cast<float4*>(g_hn + v0 * 64);
    #pragma unroll
    for (int i = 0; i < 2; i++) {
        int idx = t + i * 256;
        if (idx < lim4) {
            float s = nds[idx >> 4];
            float4 hv = hs4[idx];
            hng[idx] = make_float4(s * hv.x, s * hv.y, s * hv.z, s * hv.w);
        }
    }

    // gate dots: thread = (node v = t>>3, k = t&7), hh = k&3, part = k>>2
    const int v = t >> 3, k = t & 7, hh = k & 3, part = k >> 2;
    const float4* hv4 = reinterpret_cast<const float4*>(hs + v * 64);
    const float4* w4 = reinterpret_cast<const float4*>(ws + hh * 128 + part * 64);
    float acc = 0.0f;
    #pragma unroll
    for (int i = 0; i < 16; i++) {
        float4 a = hv4[i], b = w4[i];
        acc += a.x * b.x + a.y * b.y + a.z * b.z + a.w * b.w;
    }
    if (v < nval) {
        if (part == 0) g_a[(v0 + v) * 4 + hh] = acc;
        else           g_bp[(v0 + v) * 4 + hh] = acc;
    }
}

// ---------------------------------------------------------------------------
// K4: scatter edges into col-sorted order; single packed 16B record per edge
//     {row, gates01:half2, gates23:half2}
// ---------------------------------------------------------------------------
__global__ void k_scatter(const int* __restrict__ ei,
                          const float* __restrict__ gate_b) {
    int e = blockIdx.x * blockDim.x + threadIdx.x;
    if (e >= EE) return;
    int row = ei[e];
    int col = ei[EE + e];
    float4 a  = *reinterpret_cast<const float4*>(g_a + row * 4);
    float4 bp = *reinterpret_cast<const float4*>(g_bp + col * 4);
    float4 gb = *reinterpret_cast<const float4*>(gate_b);
    float gx = fast_tanh(a.x + bp.x + gb.x);
    float gy = fast_tanh(a.y + bp.y + gb.y);
    float gz = fast_tanh(a.z + bp.z + gb.z);
    float gw = fast_tanh(a.w + bp.w + gb.w);
    __half2 h01 = __floats2half2_rn(gx, gy);
    __half2 h23 = __floats2half2_rn(gz, gw);
    int4 rec;
    rec.x = row;
    rec.y = *reinterpret_cast<int*>(&h01);
    rec.z = *reinterpret_cast<int*>(&h23);
    rec.w = 0;
    int pos = atomicAdd(&g_cursor[col], 1);
    g_edge[pos] = rec;
}

// ---------------------------------------------------------------------------
// K5: segment reduction, 2 nodes per warp (16 lanes each), no atomics,
//     no shuffles: per edge, one broadcast 16B record load + one LDG.128
//     of hn[row] per lane and 8 FFMA2. Writes s[n] (fp32) to global.
// ---------------------------------------------------------------------------
__global__ __launch_bounds__(256) void k_gather() {
    const int t = threadIdx.x, lane = t & 31;
    const int half = lane >> 4, hl = lane & 15;
    const int n = blockIdx.x * 16 + ((t >> 5) << 1) + half;   // NN % 16 == 0

    const int beg = g_off[n], end = g_off[n + 1];
    const float ndc = g_nd[n];

    unsigned long long acc[8];
    #pragma unroll
    for (int i = 0; i < 8; i++) acc[i] = 0ULL;

    for (int base = beg; base < end; base += 4) {
        const int cnt = end - base;
        #pragma unroll
        for (int j = 0; j < 4; j++) {
            if (j < cnt) {
                const int4 er = g_edge[base + j];          // broadcast, 1 sector
                const int rj = er.x;
                __half2 h01 = *reinterpret_cast<const __half2*>(&er.y);
                __half2 h23 = *reinterpret_cast<const __half2*>(&er.z);
                float2 g01 = __half22float2(h01);
                float2 g23 = __half22float2(h23);
                const ulonglong2 hv =
                    *reinterpret_cast<const ulonglong2*>(g_hn + rj * 64 + 4 * hl);
                unsigned long long gp;
                gp = pack2(g01.x, g01.x); ffma2(acc[0], gp, hv.x); ffma2(acc[1], gp, hv.y);
                gp = pack2(g01.y, g01.y); ffma2(acc[2], gp, hv.x); ffma2(acc[3], gp, hv.y);
                gp = pack2(g23.x, g23.x); ffma2(acc[4], gp, hv.x); ffma2(acc[5], gp, hv.y);
                gp = pack2(g23.y, g23.y); ffma2(acc[6], gp, hv.x); ffma2(acc[7], gp, hv.y);
            }
        }
    }

    float* sp = g_s + n * 256 + 4 * hl;
    #pragma unroll
    for (int h2 = 0; h2 < 4; h2++) {
        float lo0, hi0, lo1, hi1;
        unpack2(acc[h2 * 2],     lo0, hi0);
        unpack2(acc[h2 * 2 + 1], lo1, hi1);
        *reinterpret_cast<float4*>(sp + h2 * 64) =
            make_float4(ndc * lo0, ndc * hi0, ndc * lo1, ndc * hi1);
    }
}

// ---------------------------------------------------------------------------
// K6: out = relu(s @ W_cat^T + b_cat), FFMA2, repacked-W coalesced preload.
//     Also re-zeroes the degree/count scratch for the next graph replay.
//     block: 256 threads, 16 nodes; thread = (o = t&63, k-quarter = t>>6)
// ---------------------------------------------------------------------------
__global__ __launch_bounds__(256) void k_proj(const float* __restrict__ b_cat,
                                              float* __restrict__ out) {
    __shared__ float s_sh[16][256];
    __shared__ float red[3][16][64];
    const int t = threadIdx.x;
    const int v0 = blockIdx.x * 16;

    // counter re-zero for next replay (all readers of g_degi/g_cnt are done)
    {
        int gi = blockIdx.x * 256 + t;
        if (gi < NN) { g_degi[gi] = 0; g_cnt[gi] = 0; }
    }

    const float4* sg = reinterpret_cast<const float4*>(g_s + v0 * 256);
    float4* ss4 = reinterpret_cast<float4*>(&s_sh[0][0]);
    #pragma unroll
    for (int i = 0; i < 4; i++) ss4[t + i * 256] = sg[t + i * 256];
    __syncthreads();

    const int o = t & 63, qr = t >> 6;
    const ulonglong2* wp = reinterpret_cast<const ulonglong2*>(g_wp);
    ulonglong2 wr[16];
    #pragma unroll
    for (int kk = 0; kk < 16; kk++) wr[kk] = wp[(kk * 4 + qr) * 64 + o];

    unsigned long long accP[16];
    #pragma unroll
    for (int v = 0; v < 16; v++) accP[v] = 0ULL;

    #pragma unroll
    for (int kk = 0; kk < 16; kk++) {
        ulonglong2 w2 = wr[kk];
        #pragma unroll
        for (int v = 0; v < 16; v++) {
            ulonglong2 sv = *reinterpret_cast<const ulonglong2*>(
                &s_sh[v][qr * 64 + kk * 4]);
            ffma2(accP[v], w2.x, sv.x);
            ffma2(accP[v], w2.y, sv.y);
        }
    }

    float acc[16];
    #pragma unroll
    for (int v = 0; v < 16; v++) {
        float lo, hi;
        unpack2(accP[v], lo, hi);
        acc[v] = lo + hi;
    }

    if (qr > 0) {
        #pragma unroll
        for (int v = 0; v < 16; v++) red[qr - 1][v][o] = acc[v];
    }
    __syncthreads();
    if (qr == 0) {
        float b = b_cat[o];
        #pragma unroll
        for (int v = 0; v < 16; v++) {
            float sum = acc[v] + red[0][v][o] + red[1][v][o] + red[2][v][o] + b;
            out[(v0 + v) * 64 + o] = fmaxf(sum, 0.0f);
        }
    }
}

// ---------------------------------------------------------------------------
extern "C" void kernel_launch(void* const* d_in, const int* in_sizes, int n_in,
                              void* d_out, int out_size) {
    const float* h      = (const float*)d_in[0];
    const int*   ei     = (const int*)d_in[1];
    const float* gate_w = (const float*)d_in[2];
    const float* gate_b = (const float*)d_in[3];
    const float* W_cat  = (const float*)d_in[4];
    const float* b_cat  = (const float*)d_in[5];
    float* out = (float*)d_out;

    k_count<<<(EE + 255) / 256, 256>>>(ei, W_cat);
    k_scan1<<<NSB, 256>>>();
    k_scan_node<<<NSB + NODEB, 256>>>(h, gate_w);
    k_scatter<<<(EE + 255) / 256, 256>>>(ei, gate_b);
    k_gather<<<NN / 16, 256>>>();
    k_proj<<<NN / 16, 256>>>(b_cat, out);
}

// round 12
// speedup vs baseline: 1.0720x; 1.0415x over previous
#include <cuda_runtime.h>
#include <cuda_fp16.h>

#define NN 50000
#define EE 800000
#define DD 64
#define HH 4
#define OUTD 64
#define CAP 64                   // per-node bucket capacity (P(deg>=64) ~ 1e-19)
#define EB  ((EE + 255) / 256)   // 3125 edge-phase blocks
#define NODEB ((NN + 31) / 32)   // 1563 node-phase blocks
#define WB 16                    // W-repack blocks

// ---------------------------------------------------------------------------
// Scratch (__device__ globals: allocation-free, zero-initialized at load;
// k_proj re-zeroes the counters every launch so each graph replay starts clean)
// ---------------------------------------------------------------------------
__device__ int    g_degi[NN];        // out-degree over row (deg for nd)
__device__ int    g_cursor[NN];      // bucket cursors == in-degree by col
__device__ int4   g_edge[NN * CAP];  // {row, (g*ndr)01:half2, (g*ndr)23:half2, pad}
__device__ float  g_a[NN * HH];      // h[v] . w1_h
__device__ float  g_bp[NN * HH];     // h[v] . w2_h
__device__ float  g_s[NN * HH * DD]; // aggregated (pre-projection) messages
__device__ float4 g_wp[4096];        // repacked W_cat: wp[(kk*4+qr)*64+o]

// ---------------------------------------------------------------------------
// packed f32x2 helpers (FFMA2)
// ---------------------------------------------------------------------------
__device__ __forceinline__ unsigned long long pack2(float a, float b) {
    unsigned long long r;
    asm("mov.b64 %0, {%1, %2};" : "=l"(r) : "f"(a), "f"(b));
    return r;
}
__device__ __forceinline__ void ffma2(unsigned long long& d,
                                      unsigned long long a, unsigned long long b) {
    asm("fma.rn.f32x2 %0, %1, %2, %3;" : "=l"(d) : "l"(a), "l"(b), "l"(d));
}
__device__ __forceinline__ void unpack2(unsigned long long v, float& lo, float& hi) {
    asm("mov.b64 {%0, %1}, %2;" : "=f"(lo), "=f"(hi) : "l"(v));
}

// fast tanh: 1 - 2/(exp(2x)+1); MUFU.EX2 + MUFU.RCP, correct at +/-inf
__device__ __forceinline__ float fast_tanh(float x) {
    float e = __expf(2.0f * x);
    return 1.0f - __fdividef(2.0f, e + 1.0f);
}

// ---------------------------------------------------------------------------
// K1 (k_pre), three disjoint block ranges:
//   [0, EB):            row out-degree count
//   [EB, EB+NODEB):     per-node gate projections a/bp (smem-staged)
//   [EB+NODEB, +WB):    W_cat repack into lane-consecutive layout
// ---------------------------------------------------------------------------
__global__ __launch_bounds__(256) void k_pre(const int* __restrict__ ei,
                                             const float* __restrict__ h,
                                             const float* __restrict__ gate_w,
                                             const float* __restrict__ W_cat) {
    const int t = threadIdx.x;

    if (blockIdx.x < EB) {
        int e = blockIdx.x * 256 + t;
        if (e < EE) atomicAdd(&g_degi[ei[e]], 1);
        return;
    }
    if (blockIdx.x >= EB + NODEB) {
        int i = (blockIdx.x - EB - NODEB) * 256 + t;   // 16*256 = 4096
        int o = i & 63, qr = (i >> 6) & 3, kk = i >> 8;
        g_wp[i] = *reinterpret_cast<const float4*>(W_cat + o * 256 + qr * 64 + kk * 4);
        return;
    }

    // ---- node phase: a/bp gate projections ----
    __shared__ float hs[32 * 64];
    __shared__ float ws[512];
    const int v0 = (blockIdx.x - EB) * 32;
    const int nval = (NN - v0 < 32) ? (NN - v0) : 32;
    const int lim4 = nval * 16;   // valid float4 count

    const float4* hg = reinterpret_cast<const float4*>(h + v0 * 64);
    float4* hs4 = reinterpret_cast<float4*>(hs);
    hs4[t]       = (t < lim4)       ? hg[t]       : make_float4(0, 0, 0, 0);
    hs4[t + 256] = (t + 256 < lim4) ? hg[t + 256] : make_float4(0, 0, 0, 0);
    if (t < 128) reinterpret_cast<float4*>(ws)[t] =
        reinterpret_cast<const float4*>(gate_w)[t];
    __syncthreads();

    // gate dots: thread = (node v = t>>3, k = t&7), hh = k&3, part = k>>2
    const int v = t >> 3, k = t & 7, hh = k & 3, part = k >> 2;
    const float4* hv4 = reinterpret_cast<const float4*>(hs + v * 64);
    const float4* w4 = reinterpret_cast<const float4*>(ws + hh * 128 + part * 64);
    float acc = 0.0f;
    #pragma unroll
    for (int i = 0; i < 16; i++) {
        float4 a = hv4[i], b = w4[i];
        acc += a.x * b.x + a.y * b.y + a.z * b.z + a.w * b.w;
    }
    if (v < nval) {
        if (part == 0) g_a[(v0 + v) * 4 + hh] = acc;
        else           g_bp[(v0 + v) * 4 + hh] = acc;
    }
}

// ---------------------------------------------------------------------------
// K2: scatter edges into per-col buckets; record = {row, (g*nd_row) fp16 x4}
// ---------------------------------------------------------------------------
__global__ void k_scatter(const int* __restrict__ ei,
                          const float* __restrict__ gate_b) {
    int e = blockIdx.x * blockDim.x + threadIdx.x;
    if (e >= EE) return;
    int row = ei[e];
    int col = ei[EE + e];
    float4 a  = *reinterpret_cast<const float4*>(g_a + row * 4);
    float4 bp = *reinterpret_cast<const float4*>(g_bp + col * 4);
    float4 gb = *reinterpret_cast<const float4*>(gate_b);
    float ndr = rsqrtf(fmaxf((float)g_degi[row], 1.0f));
    float gx = fast_tanh(a.x + bp.x + gb.x) * ndr;
    float gy = fast_tanh(a.y + bp.y + gb.y) * ndr;
    float gz = fast_tanh(a.z + bp.z + gb.z) * ndr;
    float gw = fast_tanh(a.w + bp.w + gb.w) * ndr;
    __half2 h01 = __floats2half2_rn(gx, gy);
    __half2 h23 = __floats2half2_rn(gz, gw);
    int4 rec;
    rec.x = row;
    rec.y = *reinterpret_cast<int*>(&h01);
    rec.z = *reinterpret_cast<int*>(&h23);
    rec.w = 0;
    int slot = atomicAdd(&g_cursor[col], 1);
    g_edge[col * CAP + slot] = rec;
}

// ---------------------------------------------------------------------------
// K3: segment reduction, 2 nodes per warp (16 lanes each), no atomics,
//     no shuffles: per edge, one broadcast 16B record (contiguous bucket)
//     + one LDG.128 of h[row] per lane, 8 FFMA2. Scales by nd_col, writes s.
// ---------------------------------------------------------------------------
__global__ __launch_bounds__(256) void k_gather(const float* __restrict__ h) {
    const int t = threadIdx.x, lane = t & 31;
    const int half = lane >> 4, hl = lane & 15;
    const int n = blockIdx.x * 16 + ((t >> 5) << 1) + half;   // NN % 16 == 0

    const int cnt = g_cursor[n];
    const float ndc = rsqrtf(fmaxf((float)g_degi[n], 1.0f));
    const int4* __restrict__ ep = g_edge + n * CAP;

    unsigned long long acc[8];
    #pragma unroll
    for (int i = 0; i < 8; i++) acc[i] = 0ULL;

    for (int base = 0; base < cnt; base += 4) {
        const int rem = cnt - base;
        #pragma unroll
        for (int j = 0; j < 4; j++) {
            if (j < rem) {
                const int4 er = ep[base + j];              // broadcast, 1 sector
                const int rj = er.x;
                __half2 h01 = *reinterpret_cast<const __half2*>(&er.y);
                __half2 h23 = *reinterpret_cast<const __half2*>(&er.z);
                float2 g01 = __half22float2(h01);
                float2 g23 = __half22float2(h23);
                const ulonglong2 hv =
                    *reinterpret_cast<const ulonglong2*>(h + rj * 64 + 4 * hl);
                unsigned long long gp;
                gp = pack2(g01.x, g01.x); ffma2(acc[0], gp, hv.x); ffma2(acc[1], gp, hv.y);
                gp = pack2(g01.y, g01.y); ffma2(acc[2], gp, hv.x); ffma2(acc[3], gp, hv.y);
                gp = pack2(g23.x, g23.x); ffma2(acc[4], gp, hv.x); ffma2(acc[5], gp, hv.y);
                gp = pack2(g23.y, g23.y); ffma2(acc[6], gp, hv.x); ffma2(acc[7], gp, hv.y);
            }
        }
    }

    float* sp = g_s + n * 256 + 4 * hl;
    #pragma unroll
    for (int h2 = 0; h2 < 4; h2++) {
        float lo0, hi0, lo1, hi1;
        unpack2(acc[h2 * 2],     lo0, hi0);
        unpack2(acc[h2 * 2 + 1], lo1, hi1);
        *reinterpret_cast<float4*>(sp + h2 * 64) =
            make_float4(ndc * lo0, ndc * hi0, ndc * lo1, ndc * hi1);
    }
}

// ---------------------------------------------------------------------------
// K4: out = relu(s @ W_cat^T + b_cat), FFMA2, repacked-W coalesced preload.
//     Also re-zeroes deg/cursor scratch for the next graph replay.
//     block: 256 threads, 16 nodes; thread = (o = t&63, k-quarter = t>>6)
// ---------------------------------------------------------------------------
__global__ __launch_bounds__(256) void k_proj(const float* __restrict__ b_cat,
                                              float* __restrict__ out) {
    __shared__ float s_sh[16][256];
    __shared__ float red[3][16][64];
    const int t = threadIdx.x;
    const int v0 = blockIdx.x * 16;

    // counter re-zero for next replay (all readers of g_degi/g_cursor are done)
    {
        int gi = blockIdx.x * 256 + t;
        if (gi < NN) { g_degi[gi] = 0; g_cursor[gi] = 0; }
    }

    const float4* sg = reinterpret_cast<const float4*>(g_s + v0 * 256);
    float4* ss4 = reinterpret_cast<float4*>(&s_sh[0][0]);
    #pragma unroll
    for (int i = 0; i < 4; i++) ss4[t + i * 256] = sg[t + i * 256];
    __syncthreads();

    const int o = t & 63, qr = t >> 6;
    const ulonglong2* wp = reinterpret_cast<const ulonglong2*>(g_wp);
    ulonglong2 wr[16];
    #pragma unroll
    for (int kk = 0; kk < 16; kk++) wr[kk] = wp[(kk * 4 + qr) * 64 + o];

    unsigned long long accP[16];
    #pragma unroll
    for (int v = 0; v < 16; v++) accP[v] = 0ULL;

    #pragma unroll
    for (int kk = 0; kk < 16; kk++) {
        ulonglong2 w2 = wr[kk];
        #pragma unroll
        for (int v = 0; v < 16; v++) {
            ulonglong2 sv = *reinterpret_cast<const ulonglong2*>(
                &s_sh[v][qr * 64 + kk * 4]);
            ffma2(accP[v], w2.x, sv.x);
            ffma2(accP[v], w2.y, sv.y);
        }
    }

    float acc[16];
    #pragma unroll
    for (int v = 0; v < 16; v++) {
        float lo, hi;
        unpack2(accP[v], lo, hi);
        acc[v] = lo + hi;
    }

    if (qr > 0) {
        #pragma unroll
        for (int v = 0; v < 16; v++) red[qr - 1][v][o] = acc[v];
    }
    __syncthreads();
    if (qr == 0) {
        float b = b_cat[o];
        #pragma unroll
        for (int v = 0; v < 16; v++) {
            float sum = acc[v] + red[0][v][o] + red[1][v][o] + red[2][v][o] + b;
            out[(v0 + v) * 64 + o] = fmaxf(sum, 0.0f);
        }
    }
}

// ---------------------------------------------------------------------------
extern "C" void kernel_launch(void* const* d_in, const int* in_sizes, int n_in,
                              void* d_out, int out_size) {
    const float* h      = (const float*)d_in[0];
    const int*   ei     = (const int*)d_in[1];
    const float* gate_w = (const float*)d_in[2];
    const float* gate_b = (const float*)d_in[3];
    const float* W_cat  = (const float*)d_in[4];
    const float* b_cat  = (const float*)d_in[5];
    float* out = (float*)d_out;

    k_pre<<<EB + NODEB + WB, 256>>>(ei, h, gate_w, W_cat);
    k_scatter<<<(EE + 255) / 256, 256>>>(ei, gate_b);
    k_gather<<<NN / 16, 256>>>(h);
    k_proj<<<NN / 16, 256>>>(b_cat, out);
}

// round 13
// speedup vs baseline: 1.1542x; 1.0766x over previous
#include <cuda_runtime.h>
#include <cuda_fp16.h>

#define NN 50000
#define NNP 50048                // NN padded to 64-node tiles for k_proj
#define EE 800000
#define DD 64
#define HH 4
#define OUTD 64
#define CAP 64                   // per-node bucket capacity (P(deg>=64) ~ 1e-19)
#define EB  ((EE + 255) / 256)   // 3125 edge-phase blocks
#define NODEB ((NN + 31) / 32)   // 1563 node-phase blocks
#define WB 64                    // W-repack blocks (16384 floats)
#define PB (NNP / 64)            // 782 proj blocks

// ---------------------------------------------------------------------------
// Scratch (__device__ globals: allocation-free, zero-initialized at load;
// k_proj re-zeroes the counters every launch so each graph replay starts clean)
// ---------------------------------------------------------------------------
__device__ int    g_degi[NN];        // out-degree over row (deg for nd)
__device__ int    g_cursor[NN];      // bucket cursors == in-degree by col
__device__ int4   g_edge[NN * CAP];  // {row, (g*ndr)01:half2, (g*ndr)23:half2, pad}
__device__ float  g_a[NN * HH];      // h[v] . w1_h
__device__ float  g_bp[NN * HH];     // h[v] . w2_h
__device__ float  g_s[NNP * HH * DD]; // aggregated messages (padded rows stay 0)
__device__ float  g_wre[256 * 64];   // W_cat repacked k-major: wre[k*64+o]

// ---------------------------------------------------------------------------
// packed f32x2 helpers (FFMA2)
// ---------------------------------------------------------------------------
__device__ __forceinline__ unsigned long long pack2(float a, float b) {
    unsigned long long r;
    asm("mov.b64 %0, {%1, %2};" : "=l"(r) : "f"(a), "f"(b));
    return r;
}
__device__ __forceinline__ void ffma2(unsigned long long& d,
                                      unsigned long long a, unsigned long long b) {
    asm("fma.rn.f32x2 %0, %1, %2, %3;" : "=l"(d) : "l"(a), "l"(b), "l"(d));
}
__device__ __forceinline__ void unpack2(unsigned long long v, float& lo, float& hi) {
    asm("mov.b64 {%0, %1}, %2;" : "=f"(lo), "=f"(hi) : "l"(v));
}

// fast tanh: 1 - 2/(exp(2x)+1); MUFU.EX2 + MUFU.RCP, correct at +/-inf
__device__ __forceinline__ float fast_tanh(float x) {
    float e = __expf(2.0f * x);
    return 1.0f - __fdividef(2.0f, e + 1.0f);
}

// ---------------------------------------------------------------------------
// K1 (k_pre), three disjoint block ranges:
//   [0, EB):            row out-degree count
//   [EB, EB+NODEB):     per-node gate projections a/bp (smem-staged)
//   [EB+NODEB, +WB):    W_cat repack into k-major layout wre[k*64+o]
// ---------------------------------------------------------------------------
__global__ __launch_bounds__(256) void k_pre(const int* __restrict__ ei,
                                             const float* __restrict__ h,
                                             const float* __restrict__ gate_w,
                                             const float* __restrict__ W_cat) {
    const int t = threadIdx.x;

    if (blockIdx.x < EB) {
        int e = blockIdx.x * 256 + t;
        if (e < EE) atomicAdd(&g_degi[ei[e]], 1);
        return;
    }
    if (blockIdx.x >= EB + NODEB) {
        int i = (blockIdx.x - EB - NODEB) * 256 + t;   // 64*256 = 16384
        int k = i >> 6, o = i & 63;
        g_wre[i] = W_cat[o * 256 + k];
        return;
    }

    // ---- node phase: a/bp gate projections ----
    __shared__ float hs[32 * 64];
    __shared__ float ws[512];
    const int v0 = (blockIdx.x - EB) * 32;
    const int nval = (NN - v0 < 32) ? (NN - v0) : 32;
    const int lim4 = nval * 16;   // valid float4 count

    const float4* hg = reinterpret_cast<const float4*>(h + v0 * 64);
    float4* hs4 = reinterpret_cast<float4*>(hs);
    hs4[t]       = (t < lim4)       ? hg[t]       : make_float4(0, 0, 0, 0);
    hs4[t + 256] = (t + 256 < lim4) ? hg[t + 256] : make_float4(0, 0, 0, 0);
    if (t < 128) reinterpret_cast<float4*>(ws)[t] =
        reinterpret_cast<const float4*>(gate_w)[t];
    __syncthreads();

    // gate dots: thread = (node v = t>>3, k = t&7), hh = k&3, part = k>>2
    const int v = t >> 3, k = t & 7, hh = k & 3, part = k >> 2;
    const float4* hv4 = reinterpret_cast<const float4*>(hs + v * 64);
    const float4* w4 = reinterpret_cast<const float4*>(ws + hh * 128 + part * 64);
    float acc = 0.0f;
    #pragma unroll
    for (int i = 0; i < 16; i++) {
        float4 a = hv4[i], b = w4[i];
        acc += a.x * b.x + a.y * b.y + a.z * b.z + a.w * b.w;
    }
    if (v < nval) {
        if (part == 0) g_a[(v0 + v) * 4 + hh] = acc;
        else           g_bp[(v0 + v) * 4 + hh] = acc;
    }
}

// ---------------------------------------------------------------------------
// K2: scatter edges into per-col buckets; record = {row, (g*nd_row) fp16 x4}
// ---------------------------------------------------------------------------
__global__ void k_scatter(const int* __restrict__ ei,
                          const float* __restrict__ gate_b) {
    int e = blockIdx.x * blockDim.x + threadIdx.x;
    if (e >= EE) return;
    int row = ei[e];
    int col = ei[EE + e];
    float4 a  = *reinterpret_cast<const float4*>(g_a + row * 4);
    float4 bp = *reinterpret_cast<const float4*>(g_bp + col * 4);
    float4 gb = *reinterpret_cast<const float4*>(gate_b);
    float ndr = rsqrtf(fmaxf((float)g_degi[row], 1.0f));
    float gx = fast_tanh(a.x + bp.x + gb.x) * ndr;
    float gy = fast_tanh(a.y + bp.y + gb.y) * ndr;
    float gz = fast_tanh(a.z + bp.z + gb.z) * ndr;
    float gw = fast_tanh(a.w + bp.w + gb.w) * ndr;
    __half2 h01 = __floats2half2_rn(gx, gy);
    __half2 h23 = __floats2half2_rn(gz, gw);
    int4 rec;
    rec.x = row;
    rec.y = *reinterpret_cast<int*>(&h01);
    rec.z = *reinterpret_cast<int*>(&h23);
    rec.w = 0;
    int slot = atomicAdd(&g_cursor[col], 1);
    g_edge[col * CAP + slot] = rec;
}

// ---------------------------------------------------------------------------
// K3: segment reduction, 2 nodes per warp (16 lanes each), no atomics,
//     no shuffles: per edge, one broadcast 16B record (contiguous bucket)
//     + one LDG.128 of h[row] per lane, 8 FFMA2. Scales by nd_col, writes s.
// ---------------------------------------------------------------------------
__global__ __launch_bounds__(256) void k_gather(const float* __restrict__ h) {
    const int t = threadIdx.x, lane = t & 31;
    const int half = lane >> 4, hl = lane & 15;
    const int n = blockIdx.x * 16 + ((t >> 5) << 1) + half;   // NN % 16 == 0

    const int cnt = g_cursor[n];
    const float ndc = rsqrtf(fmaxf((float)g_degi[n], 1.0f));
    const int4* __restrict__ ep = g_edge + n * CAP;

    unsigned long long acc[8];
    #pragma unroll
    for (int i = 0; i < 8; i++) acc[i] = 0ULL;

    for (int base = 0; base < cnt; base += 4) {
        const int rem = cnt - base;
        #pragma unroll
        for (int j = 0; j < 4; j++) {
            if (j < rem) {
                const int4 er = ep[base + j];              // broadcast, 1 sector
                const int rj = er.x;
                __half2 h01 = *reinterpret_cast<const __half2*>(&er.y);
                __half2 h23 = *reinterpret_cast<const __half2*>(&er.z);
                float2 g01 = __half22float2(h01);
                float2 g23 = __half22float2(h23);
                const ulonglong2 hv =
                    *reinterpret_cast<const ulonglong2*>(h + rj * 64 + 4 * hl);
                unsigned long long gp;
                gp = pack2(g01.x, g01.x); ffma2(acc[0], gp, hv.x); ffma2(acc[1], gp, hv.y);
                gp = pack2(g01.y, g01.y); ffma2(acc[2], gp, hv.x); ffma2(acc[3], gp, hv.y);
                gp = pack2(g23.x, g23.x); ffma2(acc[4], gp, hv.x); ffma2(acc[5], gp, hv.y);
                gp = pack2(g23.y, g23.y); ffma2(acc[6], gp, hv.x); ffma2(acc[7], gp, hv.y);
            }
        }
    }

    float* sp = g_s + n * 256 + 4 * hl;
    #pragma unroll
    for (int h2 = 0; h2 < 4; h2++) {
        float lo0, hi0, lo1, hi1;
        unpack2(acc[h2 * 2],     lo0, hi0);
        unpack2(acc[h2 * 2 + 1], lo1, hi1);
        *reinterpret_cast<float4*>(sp + h2 * 64) =
            make_float4(ndc * lo0, ndc * hi0, ndc * lo1, ndc * hi1);
    }
}

// ---------------------------------------------------------------------------
// K4: out = relu(s @ W_cat^T + b_cat) as a register-blocked tiled GEMM.
//     Block: 64 nodes x 64 outputs, 256 threads, each owns a 4x4 tile with
//     full k=256. Per 16-k tile: stage s (transposed to k-major) + w into
//     smem; inner loop = 2 LDS.128 -> 8 FFMA2. Also re-zeroes counters.
// ---------------------------------------------------------------------------
__global__ __launch_bounds__(256) void k_proj(const float* __restrict__ b_cat,
                                              float* __restrict__ out) {
    __shared__ float s_t[16][68];   // [k][node], padded
    __shared__ float w_t[16][64];   // [k][o]
    const int t = threadIdx.x;
    const int v0 = blockIdx.x * 64;

    // counter re-zero for next replay (all readers of g_degi/g_cursor are done)
    {
        int gi = blockIdx.x * 256 + t;
        if (gi < NN) { g_degi[gi] = 0; g_cursor[gi] = 0; }
    }

    const int tx = t & 15;          // o-quad: outputs tx*4 .. tx*4+3
    const int ty = t >> 4;          // v-quad: nodes  ty*4 .. ty*4+3
    const int lv = t >> 2;          // staging node 0..63
    const int lk = (t & 3) * 4;     // staging k offset 0,4,8,12
    const int wk = t >> 4;          // w staging row 0..15
    const int wo = (t & 15) * 4;    // w staging col

    unsigned long long accP[4][2];
    #pragma unroll
    for (int i = 0; i < 4; i++) { accP[i][0] = 0ULL; accP[i][1] = 0ULL; }

    #pragma unroll 1
    for (int kt = 0; kt < 256; kt += 16) {
        float4 sv = *reinterpret_cast<const float4*>(g_s + (v0 + lv) * 256 + kt + lk);
        float4 wv = *reinterpret_cast<const float4*>(g_wre + (kt + wk) * 64 + wo);
        if (kt) __syncthreads();    // previous tile fully consumed
        s_t[lk + 0][lv] = sv.x;
        s_t[lk + 1][lv] = sv.y;
        s_t[lk + 2][lv] = sv.z;
        s_t[lk + 3][lv] = sv.w;
        *reinterpret_cast<float4*>(&w_t[wk][wo]) = wv;
        __syncthreads();

        #pragma unroll
        for (int kk = 0; kk < 16; kk++) {
            float4 a = *reinterpret_cast<const float4*>(&s_t[kk][ty * 4]);
            float4 b = *reinterpret_cast<const float4*>(&w_t[kk][tx * 4]);
            unsigned long long b01 = pack2(b.x, b.y);
            unsigned long long b23 = pack2(b.z, b.w);
            unsigned long long gp;
            gp = pack2(a.x, a.x); ffma2(accP[0][0], gp, b01); ffma2(accP[0][1], gp, b23);
            gp = pack2(a.y, a.y); ffma2(accP[1][0], gp, b01); ffma2(accP[1][1], gp, b23);
            gp = pack2(a.z, a.z); ffma2(accP[2][0], gp, b01); ffma2(accP[2][1], gp, b23);
            gp = pack2(a.w, a.w); ffma2(accP[3][0], gp, b01); ffma2(accP[3][1], gp, b23);
        }
    }

    const float4 bb = *reinterpret_cast<const float4*>(b_cat + tx * 4);
    #pragma unroll
    for (int i = 0; i < 4; i++) {
        int n = v0 + ty * 4 + i;
        if (n < NN) {
            float o0, o1, o2, o3;
            unpack2(accP[i][0], o0, o1);
            unpack2(accP[i][1], o2, o3);
            *reinterpret_cast<float4*>(out + n * 64 + tx * 4) =
                make_float4(fmaxf(o0 + bb.x, 0.0f), fmaxf(o1 + bb.y, 0.0f),
                            fmaxf(o2 + bb.z, 0.0f), fmaxf(o3 + bb.w, 0.0f));
        }
    }
}

// ---------------------------------------------------------------------------
extern "C" void kernel_launch(void* const* d_in, const int* in_sizes, int n_in,
                              void* d_out, int out_size) {
    const float* h      = (const float*)d_in[0];
    const int*   ei     = (const int*)d_in[1];
    const float* gate_w = (const float*)d_in[2];
    const float* gate_b = (const float*)d_in[3];
    const float* W_cat  = (const float*)d_in[4];
    const float* b_cat  = (const float*)d_in[5];
    float* out = (float*)d_out;

    k_pre<<<EB + NODEB + WB, 256>>>(ei, h, gate_w, W_cat);
    k_scatter<<<(EE + 255) / 256, 256>>>(ei, gate_b);
    k_gather<<<NN / 16, 256>>>(h);
    k_proj<<<PB, 256>>>(b_cat, out);
}

// round 14
// speedup vs baseline: 1.2082x; 1.0468x over previous
#include <cuda_runtime.h>
#include <cuda_fp16.h>

#define NN 50000
#define NNP 50048                // NN padded to 64-node tiles for k_proj
#define EE 800000
#define DD 64
#define HH 4
#define OUTD 64
#define CAP 64                   // per-node bucket capacity (P(deg>=64) ~ 1e-19)
#define EB  ((EE + 255) / 256)   // 3125 edge-phase blocks
#define NODEB ((NN + 31) / 32)   // 1563 node-phase blocks
#define WB 64                    // W-repack blocks (16384 floats)
#define PB (NNP / 64)            // 782 proj blocks

// ---------------------------------------------------------------------------
// Scratch (__device__ globals: allocation-free, zero-initialized at load;
// k_proj re-zeroes the counters every launch so each graph replay starts clean)
// ---------------------------------------------------------------------------
__device__ int    g_degi[NN];        // out-degree over row (deg for nd)
__device__ int    g_cursor[NN];      // bucket cursors == in-degree by col
__device__ int4   g_edge[NN * CAP];  // {row, (g*ndr)01:half2, (g*ndr)23:half2, pad}
__device__ float  g_a[NN * HH];      // h[v] . w1_h
__device__ float  g_bp[NN * HH];     // h[v] . w2_h
__device__ __half g_sh[NNP * HH * DD]; // aggregated messages, fp16 (padded rows 0)
__device__ float  g_wre[256 * 64];   // W_cat repacked k-major: wre[k*64+o]

// ---------------------------------------------------------------------------
// packed f32x2 helpers (FFMA2)
// ---------------------------------------------------------------------------
__device__ __forceinline__ unsigned long long pack2(float a, float b) {
    unsigned long long r;
    asm("mov.b64 %0, {%1, %2};" : "=l"(r) : "f"(a), "f"(b));
    return r;
}
__device__ __forceinline__ void ffma2(unsigned long long& d,
                                      unsigned long long a, unsigned long long b) {
    asm("fma.rn.f32x2 %0, %1, %2, %3;" : "=l"(d) : "l"(a), "l"(b), "l"(d));
}
__device__ __forceinline__ void unpack2(unsigned long long v, float& lo, float& hi) {
    asm("mov.b64 {%0, %1}, %2;" : "=f"(lo), "=f"(hi) : "l"(v));
}

// fast tanh: 1 - 2/(exp(2x)+1); MUFU.EX2 + MUFU.RCP, correct at +/-inf
__device__ __forceinline__ float fast_tanh(float x) {
    float e = __expf(2.0f * x);
    return 1.0f - __fdividef(2.0f, e + 1.0f);
}

// ---------------------------------------------------------------------------
// K1 (k_pre), three disjoint block ranges:
//   [0, EB):            row out-degree count
//   [EB, EB+NODEB):     per-node gate projections a/bp (smem-staged)
//   [EB+NODEB, +WB):    W_cat repack into k-major layout wre[k*64+o]
// ---------------------------------------------------------------------------
__global__ __launch_bounds__(256) void k_pre(const int* __restrict__ ei,
                                             const float* __restrict__ h,
                                             const float* __restrict__ gate_w,
                                             const float* __restrict__ W_cat) {
    const int t = threadIdx.x;

    if (blockIdx.x < EB) {
        int e = blockIdx.x * 256 + t;
        if (e < EE) atomicAdd(&g_degi[ei[e]], 1);
        return;
    }
    if (blockIdx.x >= EB + NODEB) {
        int i = (blockIdx.x - EB - NODEB) * 256 + t;   // 64*256 = 16384
        int k = i >> 6, o = i & 63;
        g_wre[i] = W_cat[o * 256 + k];
        return;
    }

    // ---- node phase: a/bp gate projections ----
    __shared__ float hs[32 * 64];
    __shared__ float ws[512];
    const int v0 = (blockIdx.x - EB) * 32;
    const int nval = (NN - v0 < 32) ? (NN - v0) : 32;
    const int lim4 = nval * 16;   // valid float4 count

    const float4* hg = reinterpret_cast<const float4*>(h + v0 * 64);
    float4* hs4 = reinterpret_cast<float4*>(hs);
    hs4[t]       = (t < lim4)       ? hg[t]       : make_float4(0, 0, 0, 0);
    hs4[t + 256] = (t + 256 < lim4) ? hg[t + 256] : make_float4(0, 0, 0, 0);
    if (t < 128) reinterpret_cast<float4*>(ws)[t] =
        reinterpret_cast<const float4*>(gate_w)[t];
    __syncthreads();

    // gate dots: thread = (node v = t>>3, k = t&7), hh = k&3, part = k>>2
    const int v = t >> 3, k = t & 7, hh = k & 3, part = k >> 2;
    const float4* hv4 = reinterpret_cast<const float4*>(hs + v * 64);
    const float4* w4 = reinterpret_cast<const float4*>(ws + hh * 128 + part * 64);
    float acc = 0.0f;
    #pragma unroll
    for (int i = 0; i < 16; i++) {
        float4 a = hv4[i], b = w4[i];
        acc += a.x * b.x + a.y * b.y + a.z * b.z + a.w * b.w;
    }
    if (v < nval) {
        if (part == 0) g_a[(v0 + v) * 4 + hh] = acc;
        else           g_bp[(v0 + v) * 4 + hh] = acc;
    }
}

// ---------------------------------------------------------------------------
// K2: scatter edges into per-col buckets; record = {row, (g*nd_row) fp16 x4}
// ---------------------------------------------------------------------------
__global__ void k_scatter(const int* __restrict__ ei,
                          const float* __restrict__ gate_b) {
    int e = blockIdx.x * blockDim.x + threadIdx.x;
    if (e >= EE) return;
    int row = ei[e];
    int col = ei[EE + e];
    float4 a  = *reinterpret_cast<const float4*>(g_a + row * 4);
    float4 bp = *reinterpret_cast<const float4*>(g_bp + col * 4);
    float4 gb = *reinterpret_cast<const float4*>(gate_b);
    float ndr = rsqrtf(fmaxf((float)g_degi[row], 1.0f));
    float gx = fast_tanh(a.x + bp.x + gb.x) * ndr;
    float gy = fast_tanh(a.y + bp.y + gb.y) * ndr;
    float gz = fast_tanh(a.z + bp.z + gb.z) * ndr;
    float gw = fast_tanh(a.w + bp.w + gb.w) * ndr;
    __half2 h01 = __floats2half2_rn(gx, gy);
    __half2 h23 = __floats2half2_rn(gz, gw);
    int4 rec;
    rec.x = row;
    rec.y = *reinterpret_cast<int*>(&h01);
    rec.z = *reinterpret_cast<int*>(&h23);
    rec.w = 0;
    int slot = atomicAdd(&g_cursor[col], 1);
    g_edge[col * CAP + slot] = rec;
}

// ---------------------------------------------------------------------------
// K3: segment reduction, 2 nodes per warp (16 lanes each), no atomics,
//     no shuffles: per edge, one broadcast 16B record (contiguous bucket)
//     + one LDG.128 of h[row] per lane, 8 FFMA2. fp32 accumulate; fp16 store.
// ---------------------------------------------------------------------------
__global__ __launch_bounds__(256) void k_gather(const float* __restrict__ h) {
    const int t = threadIdx.x, lane = t & 31;
    const int half = lane >> 4, hl = lane & 15;
    const int n = blockIdx.x * 16 + ((t >> 5) << 1) + half;   // NN % 16 == 0

    const int cnt = g_cursor[n];
    const float ndc = rsqrtf(fmaxf((float)g_degi[n], 1.0f));
    const int4* __restrict__ ep = g_edge + n * CAP;

    unsigned long long acc[8];
    #pragma unroll
    for (int i = 0; i < 8; i++) acc[i] = 0ULL;

    for (int base = 0; base < cnt; base += 4) {
        const int rem = cnt - base;
        #pragma unroll
        for (int j = 0; j < 4; j++) {
            if (j < rem) {
                const int4 er = ep[base + j];              // broadcast, 1 sector
                const int rj = er.x;
                __half2 h01 = *reinterpret_cast<const __half2*>(&er.y);
                __half2 h23 = *reinterpret_cast<const __half2*>(&er.z);
                float2 g01 = __half22float2(h01);
                float2 g23 = __half22float2(h23);
                const ulonglong2 hv =
                    *reinterpret_cast<const ulonglong2*>(h + rj * 64 + 4 * hl);
                unsigned long long gp;
                gp = pack2(g01.x, g01.x); ffma2(acc[0], gp, hv.x); ffma2(acc[1], gp, hv.y);
                gp = pack2(g01.y, g01.y); ffma2(acc[2], gp, hv.x); ffma2(acc[3], gp, hv.y);
                gp = pack2(g23.x, g23.x); ffma2(acc[4], gp, hv.x); ffma2(acc[5], gp, hv.y);
                gp = pack2(g23.y, g23.y); ffma2(acc[6], gp, hv.x); ffma2(acc[7], gp, hv.y);
            }
        }
    }

    __half* sp = g_sh + n * 256 + 4 * hl;
    #pragma unroll
    for (int h2 = 0; h2 < 4; h2++) {
        float lo0, hi0, lo1, hi1;
        unpack2(acc[h2 * 2],     lo0, hi0);
        unpack2(acc[h2 * 2 + 1], lo1, hi1);
        __half2 p0 = __floats2half2_rn(ndc * lo0, ndc * hi0);
        __half2 p1 = __floats2half2_rn(ndc * lo1, ndc * hi1);
        uint2 pk;
        pk.x = *reinterpret_cast<unsigned*>(&p0);
        pk.y = *reinterpret_cast<unsigned*>(&p1);
        *reinterpret_cast<uint2*>(sp + h2 * 64) = pk;
    }
}

// ---------------------------------------------------------------------------
// K4: out = relu(s @ W_cat^T + b_cat) as a register-blocked tiled GEMM with
//     software pipelining. Block: 64 nodes x 64 outputs, 256 threads, each
//     owns a 4x4 tile, full k=256. s read as fp16 (25.6MB stream), w from
//     L2-resident repack. Prefetch tile k+1 before computing tile k.
// ---------------------------------------------------------------------------
__global__ __launch_bounds__(256) void k_proj(const float* __restrict__ b_cat,
                                              float* __restrict__ out) {
    __shared__ float s_t[16][68];   // [k][node], padded
    __shared__ float w_t[16][64];   // [k][o]
    const int t = threadIdx.x;
    const int v0 = blockIdx.x * 64;

    // counter re-zero for next replay (all readers of g_degi/g_cursor are done)
    {
        int gi = blockIdx.x * 256 + t;
        if (gi < NN) { g_degi[gi] = 0; g_cursor[gi] = 0; }
    }

    const int tx = t & 15;          // o-quad: outputs tx*4 .. tx*4+3
    const int ty = t >> 4;          // v-quad: nodes  ty*4 .. ty*4+3
    const int lv = t >> 2;          // staging node 0..63
    const int lk = (t & 3) * 4;     // staging k offset 0,4,8,12
    const int wk = t >> 4;          // w staging row 0..15
    const int wo = (t & 15) * 4;    // w staging col

    const __half* __restrict__ srow = g_sh + (v0 + lv) * 256 + lk;

    unsigned long long accP[4][2];
    #pragma unroll
    for (int i = 0; i < 4; i++) { accP[i][0] = 0ULL; accP[i][1] = 0ULL; }

    // prefetch tile 0
    uint2  sv = *reinterpret_cast<const uint2*>(srow);
    float4 wv = *reinterpret_cast<const float4*>(g_wre + wk * 64 + wo);

    #pragma unroll 1
    for (int kt = 0; kt < 256; kt += 16) {
        // stage prefetched tile
        {
            __half2 p0 = *reinterpret_cast<__half2*>(&sv.x);
            __half2 p1 = *reinterpret_cast<__half2*>(&sv.y);
            float2 f0 = __half22float2(p0);
            float2 f1 = __half22float2(p1);
            s_t[lk + 0][lv] = f0.x;
            s_t[lk + 1][lv] = f0.y;
            s_t[lk + 2][lv] = f1.x;
            s_t[lk + 3][lv] = f1.y;
            *reinterpret_cast<float4*>(&w_t[wk][wo]) = wv;
        }
        __syncthreads();

        // prefetch next tile (issued before compute so DRAM latency hides)
        if (kt < 240) {
            sv = *reinterpret_cast<const uint2*>(srow + kt + 16);
            wv = *reinterpret_cast<const float4*>(g_wre + (kt + 16 + wk) * 64 + wo);
        }

        #pragma unroll
        for (int kk = 0; kk < 16; kk++) {
            float4 a = *reinterpret_cast<const float4*>(&s_t[kk][ty * 4]);
            float4 b = *reinterpret_cast<const float4*>(&w_t[kk][tx * 4]);
            unsigned long long b01 = pack2(b.x, b.y);
            unsigned long long b23 = pack2(b.z, b.w);
            unsigned long long gp;
            gp = pack2(a.x, a.x); ffma2(accP[0][0], gp, b01); ffma2(accP[0][1], gp, b23);
            gp = pack2(a.y, a.y); ffma2(accP[1][0], gp, b01); ffma2(accP[1][1], gp, b23);
            gp = pack2(a.z, a.z); ffma2(accP[2][0], gp, b01); ffma2(accP[2][1], gp, b23);
            gp = pack2(a.w, a.w); ffma2(accP[3][0], gp, b01); ffma2(accP[3][1], gp, b23);
        }
        __syncthreads();
    }

    const float4 bb = *reinterpret_cast<const float4*>(b_cat + tx * 4);
    #pragma unroll
    for (int i = 0; i < 4; i++) {
        int n = v0 + ty * 4 + i;
        if (n < NN) {
            float o0, o1, o2, o3;
            unpack2(accP[i][0], o0, o1);
            unpack2(accP[i][1], o2, o3);
            *reinterpret_cast<float4*>(out + n * 64 + tx * 4) =
                make_float4(fmaxf(o0 + bb.x, 0.0f), fmaxf(o1 + bb.y, 0.0f),
                            fmaxf(o2 + bb.z, 0.0f), fmaxf(o3 + bb.w, 0.0f));
        }
    }
}

// ---------------------------------------------------------------------------
extern "C" void kernel_launch(void* const* d_in, const int* in_sizes, int n_in,
                              void* d_out, int out_size) {
    const float* h      = (const float*)d_in[0];
    const int*   ei     = (const int*)d_in[1];
    const float* gate_w = (const float*)d_in[2];
    const float* gate_b = (const float*)d_in[3];
    const float* W_cat  = (const float*)d_in[4];
    const float* b_cat  = (const float*)d_in[5];
    float* out = (float*)d_out;

    k_pre<<<EB + NODEB + WB, 256>>>(ei, h, gate_w, W_cat);
    k_scatter<<<(EE + 255) / 256, 256>>>(ei, gate_b);
    k_gather<<<NN / 16, 256>>>(h);
    k_proj<<<PB, 256>>>(b_cat, out);
}